// round 6
// baseline (speedup 1.0000x reference)
#include <cuda_runtime.h>
#include <cstdint>

#define BB 64
#define SS 512
#define HH 768
#define KK 21
#define FULLMASK 0xffffffffu
#define LOG21 3.0445224377234229f

// ---------------------------------------------------------------------------
// helpers
// ---------------------------------------------------------------------------
__device__ __forceinline__ void fma2(unsigned long long& acc,
                                     unsigned long long a,
                                     unsigned long long b) {
    asm("fma.rn.f32x2 %0, %1, %2, %0;" : "+l"(acc) : "l"(a), "l"(b));
}
__device__ __forceinline__ float2 unpack2(unsigned long long v) {
    float lo, hi;
    asm("mov.b64 {%0,%1}, %2;" : "=f"(lo), "=f"(hi) : "l"(v));
    return make_float2(lo, hi);
}
__device__ __forceinline__ float rcpa(float x) {
    float r;
    asm("rcp.approx.f32 %0, %1;" : "=f"(r) : "f"(x));
    return r;
}
__device__ __forceinline__ void cpa8(void* dst, const void* src) {
    uint32_t d = (uint32_t)__cvta_generic_to_shared(dst);
    asm volatile("cp.async.ca.shared.global [%0], [%1], 8;\n" ::"r"(d), "l"(src));
}
__device__ __forceinline__ void cpa16(void* dst, const void* src) {
    uint32_t d = (uint32_t)__cvta_generic_to_shared(dst);
    asm volatile("cp.async.cg.shared.global [%0], [%1], 16;\n" ::"r"(d), "l"(src));
}

__device__ float4 g_wpack[384 * 11];
__device__ float  g_partial[BB];
__device__ int    g_ctr = 0;

// CRF scan scratch
__device__ float g_a1v[BB][32];            // forward vector at q1
__device__ float g_cfv[BB];
__device__ float g_dv[BB][32];             // backward vector at q3
__device__ float g_cdv[BB];
__device__ float g_numv[BB];               // numerator + end term
__device__ float g_colsv[BB][2][KK][32];   // segment matrices (columns)
__device__ float g_lcv[BB][2][KK];         // per-column log scales
__device__ int   g_seqctr[BB];             // zero-init

// ---------------------------------------------------------------------------
// Kernel 0: pack W once
// ---------------------------------------------------------------------------
__global__ void pack_w_kernel(const float* __restrict__ Wg) {
    int idx = blockIdx.x * blockDim.x + threadIdx.x;
    if (idx >= 384 * 11) return;
    int p = idx / 11, cc = idx - p * 11;
    int c0 = 2 * cc, c1 = c0 + 1;
    float a = Wg[(2 * p)     * KK + c0];
    float b = Wg[(2 * p + 1) * KK + c0];
    float c = (c1 < KK) ? Wg[(2 * p)     * KK + c1] : 0.f;
    float d = (c1 < KK) ? Wg[(2 * p + 1) * KK + c1] : 0.f;
    g_wpack[idx] = make_float4(a, b, c, d);
}

// ---------------------------------------------------------------------------
// Kernel 1: GEMM (unchanged from R5)
// ---------------------------------------------------------------------------
#define GT    128
#define GR    128
#define GSTR  66
#define WCH   352
#define NCH   12
#define HFLOATS (GR * GSTR)
#define GSMEM (2 * HFLOATS * 4 + 2 * WCH * 16)

__global__ __launch_bounds__(GT) void gemm_kernel(
    const float* __restrict__ hidden,
    const float* __restrict__ bg,
    float* __restrict__ out) {
    extern __shared__ float dsm[];
    float*  shh = dsm;
    float4* wb  = (float4*)(dsm + 2 * HFLOATS);

    const int tid = threadIdx.x;
    const int r2 = tid & 63;
    const int h = tid >> 6;
    const size_t rowBase = (size_t)blockIdx.x * GR;

    auto LOADC = [&](int c, int buf) {
        const float* hsrc = hidden + rowBase * HH + c * 64;
        float* dst = shh + buf * HFLOATS;
#pragma unroll
        for (int j = 0; j < 32; j++) {
            int idx = tid + j * GT;
            int row = idx >> 5, u8 = idx & 31;
            cpa8(&dst[row * GSTR + u8 * 2], hsrc + (size_t)row * HH + u8 * 2);
        }
#pragma unroll
        for (int j = 0; j < 3; j++) {
            int idx = tid + j * GT;
            if (idx < WCH) cpa16(&wb[buf * WCH + idx], &g_wpack[c * WCH + idx]);
        }
        asm volatile("cp.async.commit_group;\n");
    };

    unsigned long long accA[KK], accB[KK];
#pragma unroll
    for (int i = 0; i < KK; i++) { accA[i] = 0ull; accB[i] = 0ull; }

    LOADC(0, 0);
    for (int c = 0; c < NCH; c++) {
        if (c + 1 < NCH) {
            LOADC(c + 1, (c + 1) & 1);
            asm volatile("cp.async.wait_group 1;\n");
        } else {
            asm volatile("cp.async.wait_group 0;\n");
        }
        __syncthreads();

        const float* hpA = &shh[(c & 1) * HFLOATS + r2 * GSTR + h * 32];
        const float* hpB = hpA + 64 * GSTR;
        const float4* wp = &wb[(c & 1) * WCH + (h * 16) * 11];
#pragma unroll
        for (int p = 0; p < 16; p++) {
            unsigned long long h2a = *(const unsigned long long*)&hpA[2 * p];
            unsigned long long h2b = *(const unsigned long long*)&hpB[2 * p];
            const ulonglong2* wrow = (const ulonglong2*)&wp[p * 11];
#pragma unroll
            for (int cc = 0; cc < 10; cc++) {
                ulonglong2 w2 = wrow[cc];
                fma2(accA[2 * cc],     h2a, w2.x);
                fma2(accA[2 * cc + 1], h2a, w2.y);
                fma2(accB[2 * cc],     h2b, w2.x);
                fma2(accB[2 * cc + 1], h2b, w2.y);
            }
            ulonglong2 w2 = wrow[10];
            fma2(accA[20], h2a, w2.x);
            fma2(accB[20], h2b, w2.x);
        }
        __syncthreads();
    }

    float resA[KK], resB[KK];
#pragma unroll
    for (int cc = 0; cc < KK; cc++) {
        float2 fa = unpack2(accA[cc]);
        float2 fb = unpack2(accB[cc]);
        resA[cc] = fa.x + fa.y;
        resB[cc] = fb.x + fb.y;
    }
    if (h == 1) {
#pragma unroll
        for (int cc = 0; cc < KK; cc++) {
            shh[r2 * 22 + cc] = resA[cc];
            shh[(64 + r2) * 22 + cc] = resB[cc];
        }
    }
    __syncthreads();
    float* shOut = shh + GR * 22;
    if (h == 0) {
#pragma unroll
        for (int cc = 0; cc < KK; cc++) {
            shOut[r2 * KK + cc] = resA[cc] + shh[r2 * 22 + cc] + bg[cc];
            shOut[(64 + r2) * KK + cc] =
                resB[cc] + shh[(64 + r2) * 22 + cc] + bg[cc];
        }
    }
    __syncthreads();
    float* outp = out + rowBase * KK;
#pragma unroll
    for (int j = 0; j < (GR * KK) / GT; j++) outp[tid + j * GT] = shOut[tid + j * GT];
}

// ---------------------------------------------------------------------------
// CRF primitives
// ---------------------------------------------------------------------------
#define RN 16

__device__ __forceinline__ int seq_len_w(const void* maskraw, int b, int lane) {
    const int* im = (const int*)maskraw;
    bool bytes = (im[0] != 1);
    int len = 0;
    if (!bytes) {
        const int* m = im + b * SS;
        for (int t = lane; t < SS; t += 32) len += (m[t] != 0);
    } else {
        const unsigned char* m = (const unsigned char*)maskraw + b * SS;
        for (int t = lane; t < SS; t += 32) len += (m[t] != 0);
    }
#pragma unroll
    for (int o = 16; o; o >>= 1) len += __shfl_xor_sync(FULLMASK, len, o);
    return len;
}

__device__ __forceinline__ float crf_step(float u, const float* tE, float e0) {
    float s[7];
#pragma unroll
    for (int i = 0; i < 7; i++) {
        float u0 = __shfl_sync(FULLMASK, u, 3 * i);
        float u1 = __shfl_sync(FULLMASK, u, 3 * i + 1);
        float u2 = __shfl_sync(FULLMASK, u, 3 * i + 2);
        float p = u0 * tE[3 * i];
        p = fmaf(u1, tE[3 * i + 1], p);
        p = fmaf(u2, tE[3 * i + 2], p);
        s[i] = p;
    }
    return (((s[0] + s[1]) + (s[2] + s[3])) + ((s[4] + s[5]) + s[6])) * e0;
}

// n steps; emission t-index = base + dir*stepIdx, stepIdx 0..n-1
__device__ __forceinline__ float crf_run(float u, float& logC, const float* tE,
                                         const float* lg, int jj,
                                         int base, int dir, int n) {
    if (n <= 0) return u;
    float ev[RN], evn[RN];
#pragma unroll
    for (int j = 0; j < RN; j++) {
        int idx = (j < n) ? j : n - 1;
        ev[j] = lg[(base + dir * idx) * KK + jj];
    }
    int pos = 0;
    while (pos + RN <= n) {
#pragma unroll
        for (int j = 0; j < RN; j++) {
            int idx = pos + RN + j; idx = (idx < n) ? idx : n - 1;
            evn[j] = lg[(base + dir * idx) * KK + jj];
        }
        float e0 = __expf(ev[0]);
#pragma unroll
        for (int j = 0; j < RN; j++) {
            float e1 = __expf(ev[(j + 1) & (RN - 1)]);
            u = crf_step(u, tE, e0);
            e0 = e1;
        }
        float c = __shfl_sync(FULLMASK, u, 0);
        u *= rcpa(c);
        logC += __logf(c);
#pragma unroll
        for (int j = 0; j < RN; j++) ev[j] = evn[j];
        pos += RN;
    }
    int tail = n - pos;
    for (int j = 0; j < tail; j++) {
        float e0 = __expf(ev[j]);
        u = crf_step(u, tE, e0);
    }
    if (tail) {
        float c = __shfl_sync(FULLMASK, u, 0);
        u *= rcpa(c);
        logC += __logf(c);
    }
    logC += (float)n * LOG21;
    return u;
}

// ---------------------------------------------------------------------------
// Kernel 2: 4-segment associative CRF scan. grid (BB, 4), 672 threads.
//   s=0: warp0 fwd vector (t=1..q1), warp1 numerator
//   s=1: 21 warps = columns of M_B = A_q2...A_{q1+1}
//   s=2: 21 warps = columns of M_C = A_q3...A_{q2+1}
//   s=3: warp0 bwd vector (t=len-1..q3+1)
//   Last block per sequence combines; last sequence reduces to nll.
// ---------------------------------------------------------------------------
__global__ __launch_bounds__(672) void crf_scan(
    const float* __restrict__ logits,
    const int*   __restrict__ labels,
    const void*  __restrict__ maskraw,
    const float* __restrict__ start_t,
    const float* __restrict__ trans,
    const float* __restrict__ end_t,
    float* __restrict__ out_nll) {
    const int b = blockIdx.x;
    const int s = blockIdx.y;
    const int tid = threadIdx.x;
    const int w = tid >> 5;
    const int lane = tid & 31;
    const int jj = (lane < KK) ? lane : KK - 1;

    const int len = seq_len_w(maskraw, b, lane);
    const int q1 = len >> 2, q2 = len >> 1, q3 = (3 * len) >> 2;
    const float* lg  = logits + (size_t)b * SS * KK;
    const int*   lab = labels + b * SS;

    if (s == 0) {
        if (w == 0) {
            float tE[KK];
#pragma unroll
            for (int i = 0; i < KK; i++)
                tE[i] = __expf(trans[i * KK + jj]) * (1.f / 21.f);
            float a0 = (lane < KK) ? (start_t[lane] + lg[lane]) : -1e30f;
            float m0 = a0;
#pragma unroll
            for (int o = 16; o; o >>= 1)
                m0 = fmaxf(m0, __shfl_xor_sync(FULLMASK, m0, o));
            float u = __expf(a0 - m0);
            float logC = m0;
            u = crf_run(u, logC, tE, lg, jj, 1, +1, q1);
            g_a1v[b][lane] = u;
            if (lane == 0) g_cfv[b] = logC;
        } else if (w == 1) {
            float num = 0.f;
            for (int t = lane; t < len; t += 32) {
                int lt = lab[t];
                float e = lg[t * KK + lt];
                num += (t == 0) ? (start_t[lt] + e)
                                : (e + trans[lab[t - 1] * KK + lt]);
            }
#pragma unroll
            for (int o = 16; o; o >>= 1)
                num += __shfl_xor_sync(FULLMASK, num, o);
            if (lane == 0) g_numv[b] = num + end_t[lab[len - 1]];
        }
    } else if (s == 3) {
        if (w == 0) {
            float tEb[KK];
#pragma unroll
            for (int i = 0; i < KK; i++)
                tEb[i] = __expf(trans[jj * KK + i]) * (1.f / 21.f);
            float v = __expf(end_t[jj]);
            float logC = 0.f;
            v = crf_run(v, logC, tEb, lg, jj, len - 1, -1, len - 1 - q3);
            g_dv[b][lane] = v;
            if (lane == 0) g_cdv[b] = logC;
        }
    } else {
        // s==1 / s==2 : matrix columns, warp w = column w
        float tE[KK];
#pragma unroll
        for (int i = 0; i < KK; i++)
            tE[i] = __expf(trans[i * KK + jj]) * (1.f / 21.f);
        float u = (lane == w) ? 1.f : 0.f;
        float logC = 0.f;
        int base = (s == 1) ? (q1 + 1) : (q2 + 1);
        int n    = (s == 1) ? (q2 - q1) : (q3 - q2);
        u = crf_run(u, logC, tE, lg, jj, base, +1, n);
        g_colsv[b][s - 1][w][lane] = u;
        if (lane == 0) g_lcv[b][s - 1][w] = logC;
    }

    __syncthreads();
    __shared__ int sOld;
    if (tid == 0) {
        __threadfence();
        sOld = atomicAdd(&g_seqctr[b], 1);
    }
    __syncthreads();
    if (sOld != 3 || w != 0) return;

    // -------- combine (warp 0 of last-arriving block) --------
    __threadfence();
    float a1 = g_a1v[b][lane];
    float cacc = g_cfv[b];

    // apply M_B
    {
        float lc = (lane < KK) ? g_lcv[b][0][lane] : -1e30f;
        float ref = lc;
#pragma unroll
        for (int o = 16; o; o >>= 1)
            ref = fmaxf(ref, __shfl_xor_sync(FULLMASK, ref, o));
        float sj = (lane < KK) ? a1 * expf(lc - ref) : 0.f;
        float a2 = 0.f;
#pragma unroll
        for (int j = 0; j < KK; j++) {
            float sjj = __shfl_sync(FULLMASK, sj, j);
            a2 = fmaf(sjj, g_colsv[b][0][j][lane], a2);
        }
        float c0 = __shfl_sync(FULLMASK, a2, 0);
        a2 = a2 / c0;
        cacc += ref + logf(c0);
        a1 = a2;
    }
    // apply M_C
    {
        float lc = (lane < KK) ? g_lcv[b][1][lane] : -1e30f;
        float ref = lc;
#pragma unroll
        for (int o = 16; o; o >>= 1)
            ref = fmaxf(ref, __shfl_xor_sync(FULLMASK, ref, o));
        float sj = (lane < KK) ? a1 * expf(lc - ref) : 0.f;
        float a3 = 0.f;
#pragma unroll
        for (int j = 0; j < KK; j++) {
            float sjj = __shfl_sync(FULLMASK, sj, j);
            a3 = fmaf(sjj, g_colsv[b][1][j][lane], a3);
        }
        cacc += ref;
        a1 = a3;
    }
    // dot with backward vector
    float z = (lane < KK) ? a1 * g_dv[b][lane] : 0.f;
#pragma unroll
    for (int o = 16; o; o >>= 1) z += __shfl_xor_sync(FULLMASK, z, o);
    float logZ = logf(z) + cacc + g_cdv[b];

    if (lane == 0) {
        g_partial[b] = logZ - g_numv[b];
        g_seqctr[b] = 0;                    // reset for next replay
        __threadfence();
        int old = atomicAdd(&g_ctr, 1);
        if (old == BB - 1) {
            __threadfence();
            float tot = 0.f;
            for (int i = 0; i < BB; i++) tot += g_partial[i];
            out_nll[0] = tot;
            g_ctr = 0;
        }
    }
}

// ---------------------------------------------------------------------------
extern "C" void kernel_launch(void* const* d_in, const int* in_sizes, int n_in,
                              void* d_out, int out_size) {
    const float* hidden  = (const float*)d_in[0];
    const float* W       = (const float*)d_in[1];
    const float* b       = (const float*)d_in[2];
    const float* start_t = (const float*)d_in[3];
    const float* trans   = (const float*)d_in[4];
    const float* end_t   = (const float*)d_in[5];
    const int*   labels  = (const int*)d_in[6];
    const void*  mask    = (const void*)d_in[7];

    float* out     = (float*)d_out;
    float* out_nll = out + (out_size - 1);

    cudaFuncSetAttribute(gemm_kernel,
                         cudaFuncAttributeMaxDynamicSharedMemorySize, GSMEM);

    pack_w_kernel<<<(384 * 11 + 127) / 128, 128>>>(W);
    gemm_kernel<<<(BB * SS) / GR, GT, GSMEM>>>(hidden, b, out);
    crf_scan<<<dim3(BB, 4), 672>>>(out, labels, mask, start_t, trans, end_t,
                                   out_nll);
}

// round 7
// speedup vs baseline: 1.1940x; 1.1940x over previous
#include <cuda_runtime.h>
#include <cstdint>

#define BB 64
#define SS 512
#define HH 768
#define KK 21
#define FULLMASK 0xffffffffu
#define LOG21 3.0445224377234229f

// ---------------------------------------------------------------------------
// helpers
// ---------------------------------------------------------------------------
__device__ __forceinline__ void fma2(unsigned long long& acc,
                                     unsigned long long a,
                                     unsigned long long b) {
    asm("fma.rn.f32x2 %0, %1, %2, %0;" : "+l"(acc) : "l"(a), "l"(b));
}
__device__ __forceinline__ float2 unpack2(unsigned long long v) {
    float lo, hi;
    asm("mov.b64 {%0,%1}, %2;" : "=f"(lo), "=f"(hi) : "l"(v));
    return make_float2(lo, hi);
}
__device__ __forceinline__ float rcpa(float x) {
    float r;
    asm("rcp.approx.f32 %0, %1;" : "=f"(r) : "f"(x));
    return r;
}
__device__ __forceinline__ void cpa8(void* dst, const void* src) {
    uint32_t d = (uint32_t)__cvta_generic_to_shared(dst);
    asm volatile("cp.async.ca.shared.global [%0], [%1], 8;\n" ::"r"(d), "l"(src));
}
__device__ __forceinline__ void cpa16(void* dst, const void* src) {
    uint32_t d = (uint32_t)__cvta_generic_to_shared(dst);
    asm volatile("cp.async.cg.shared.global [%0], [%1], 16;\n" ::"r"(d), "l"(src));
}

__device__ float4 g_wpack[384 * 11];
__device__ float  g_partial[BB];
__device__ int    g_ctr = 0;
__device__ int    g_packflag = 0;          // set-once: g_wpack is replay-invariant
__device__ int    g_tflag[256];            // per-tile ready flags (consumer-reset)

__device__ __forceinline__ void wait_flag(volatile int* f) {
    while (*f == 0) __nanosleep(64);
}

// ---------------------------------------------------------------------------
// GEMM config: 256 tiles of 128 rows, 128 threads, split-K x2, 2 rows/thread
// ---------------------------------------------------------------------------
#define GT    128
#define GR    128
#define GSTR  66
#define WCH   352
#define NCH   12
#define HFLOATS (GR * GSTR)
#define GSMEM (2 * HFLOATS * 4 + 2 * WCH * 16)

#define NCRFB   BB          // blocks 0..63: crf
#define PACKB   BB          // block 64: pack W
#define GEMMB0  (BB + 1)    // blocks 65..320: gemm tiles

// ---------------------------------------------------------------------------
// CRF primitives (R5 versions)
// ---------------------------------------------------------------------------
#define RN 16

__device__ __forceinline__ int seq_len_w(const void* maskraw, int b, int lane) {
    const int* im = (const int*)maskraw;
    bool bytes = (im[0] != 1);
    int len = 0;
    if (!bytes) {
        const int* m = im + b * SS;
        for (int t = lane; t < SS; t += 32) len += (m[t] != 0);
    } else {
        const unsigned char* m = (const unsigned char*)maskraw + b * SS;
        for (int t = lane; t < SS; t += 32) len += (m[t] != 0);
    }
#pragma unroll
    for (int o = 16; o; o >>= 1) len += __shfl_xor_sync(FULLMASK, len, o);
    return len;
}

__device__ __forceinline__ float crf_step(float u, const float* tE, float e0) {
    float s[7];
#pragma unroll
    for (int i = 0; i < 7; i++) {
        float u0 = __shfl_sync(FULLMASK, u, 3 * i);
        float u1 = __shfl_sync(FULLMASK, u, 3 * i + 1);
        float u2 = __shfl_sync(FULLMASK, u, 3 * i + 2);
        float p = u0 * tE[3 * i];
        p = fmaf(u1, tE[3 * i + 1], p);
        p = fmaf(u2, tE[3 * i + 2], p);
        s[i] = p;
    }
    return (((s[0] + s[1]) + (s[2] + s[3])) + ((s[4] + s[5]) + s[6])) * e0;
}

// n steps; emission t-index = base + dir*stepIdx, stepIdx 0..n-1
__device__ __forceinline__ float crf_run(float u, float& logC, const float* tE,
                                         const float* lg, int jj,
                                         int base, int dir, int n) {
    if (n <= 0) return u;
    float ev[RN], evn[RN];
#pragma unroll
    for (int j = 0; j < RN; j++) {
        int idx = (j < n) ? j : n - 1;
        ev[j] = lg[(base + dir * idx) * KK + jj];
    }
    int pos = 0;
    while (pos + RN <= n) {
#pragma unroll
        for (int j = 0; j < RN; j++) {
            int idx = pos + RN + j; idx = (idx < n) ? idx : n - 1;
            evn[j] = lg[(base + dir * idx) * KK + jj];
        }
        float e0 = __expf(ev[0]);
#pragma unroll
        for (int j = 0; j < RN; j++) {
            float e1 = __expf(ev[(j + 1) & (RN - 1)]);
            u = crf_step(u, tE, e0);
            e0 = e1;
        }
        float c = __shfl_sync(FULLMASK, u, 0);
        u *= rcpa(c);
        logC += __logf(c);
#pragma unroll
        for (int j = 0; j < RN; j++) ev[j] = evn[j];
        pos += RN;
    }
    int tail = n - pos;
    for (int j = 0; j < tail; j++) {
        float e0 = __expf(ev[j]);
        u = crf_step(u, tE, e0);
    }
    if (tail) {
        float c = __shfl_sync(FULLMASK, u, 0);
        u *= rcpa(c);
        logC += __logf(c);
    }
    logC += (float)n * LOG21;
    return u;
}

// ---------------------------------------------------------------------------
// THE fused kernel
// ---------------------------------------------------------------------------
__global__ __launch_bounds__(GT) void fused_kernel(
    const float* __restrict__ hidden,
    const float* __restrict__ Wg,
    const float* __restrict__ bg,
    const float* __restrict__ start_t,
    const float* __restrict__ trans,
    const float* __restrict__ end_t,
    const int*   __restrict__ labels,
    const void*  __restrict__ maskraw,
    float* __restrict__ out,
    float* __restrict__ out_nll) {
    extern __shared__ float dsm[];
    const int tid = threadIdx.x;
    const int bx = blockIdx.x;

    // ======================= PACK block =======================
    if (bx == PACKB) {
        for (int idx = tid; idx < 384 * 11; idx += GT) {
            int p = idx / 11, cc = idx - p * 11;
            int c0 = 2 * cc, c1 = c0 + 1;
            float a = Wg[(2 * p)     * KK + c0];
            float b = Wg[(2 * p + 1) * KK + c0];
            float c = (c1 < KK) ? Wg[(2 * p)     * KK + c1] : 0.f;
            float d = (c1 < KK) ? Wg[(2 * p + 1) * KK + c1] : 0.f;
            g_wpack[idx] = make_float4(a, b, c, d);
        }
        __threadfence();
        __syncthreads();
        if (tid == 0) atomicExch(&g_packflag, 1);
        return;
    }

    // ======================= GEMM blocks =======================
    if (bx >= GEMMB0) {
        const int g = bx - GEMMB0;           // tile index 0..255
        float*  shh = dsm;
        float4* wb  = (float4*)(dsm + 2 * HFLOATS);
        const int r2 = tid & 63;
        const int h = tid >> 6;
        const size_t rowBase = (size_t)g * GR;

        auto LOADH = [&](int c, int buf) {
            const float* hsrc = hidden + rowBase * HH + c * 64;
            float* dst = shh + buf * HFLOATS;
#pragma unroll
            for (int j = 0; j < 32; j++) {
                int idx = tid + j * GT;
                int row = idx >> 5, u8 = idx & 31;
                cpa8(&dst[row * GSTR + u8 * 2], hsrc + (size_t)row * HH + u8 * 2);
            }
        };
        auto LOADW = [&](int c, int buf) {
#pragma unroll
            for (int j = 0; j < 3; j++) {
                int idx = tid + j * GT;
                if (idx < WCH) cpa16(&wb[buf * WCH + idx], &g_wpack[c * WCH + idx]);
            }
        };

        unsigned long long accA[KK], accB[KK];
#pragma unroll
        for (int i = 0; i < KK; i++) { accA[i] = 0ull; accB[i] = 0ull; }

        // prologue: hidden chunk 0 flows while we wait for W pack
        LOADH(0, 0);
        asm volatile("cp.async.commit_group;\n");
        wait_flag(&g_packflag);
        __threadfence();
        LOADW(0, 0);
        asm volatile("cp.async.commit_group;\n");

        for (int c = 0; c < NCH; c++) {
            if (c + 1 < NCH) {
                LOADH(c + 1, (c + 1) & 1);
                LOADW(c + 1, (c + 1) & 1);
                asm volatile("cp.async.commit_group;\n");
                asm volatile("cp.async.wait_group 1;\n");
            } else {
                asm volatile("cp.async.wait_group 0;\n");
            }
            __syncthreads();

            const float* hpA = &shh[(c & 1) * HFLOATS + r2 * GSTR + h * 32];
            const float* hpB = hpA + 64 * GSTR;
            const float4* wp = &wb[(c & 1) * WCH + (h * 16) * 11];
#pragma unroll
            for (int p = 0; p < 16; p++) {
                unsigned long long h2a = *(const unsigned long long*)&hpA[2 * p];
                unsigned long long h2b = *(const unsigned long long*)&hpB[2 * p];
                const ulonglong2* wrow = (const ulonglong2*)&wp[p * 11];
#pragma unroll
                for (int cc = 0; cc < 10; cc++) {
                    ulonglong2 w2 = wrow[cc];
                    fma2(accA[2 * cc],     h2a, w2.x);
                    fma2(accA[2 * cc + 1], h2a, w2.y);
                    fma2(accB[2 * cc],     h2b, w2.x);
                    fma2(accB[2 * cc + 1], h2b, w2.y);
                }
                ulonglong2 w2 = wrow[10];
                fma2(accA[20], h2a, w2.x);
                fma2(accB[20], h2b, w2.x);
            }
            __syncthreads();
        }

        float resA[KK], resB[KK];
#pragma unroll
        for (int cc = 0; cc < KK; cc++) {
            float2 fa = unpack2(accA[cc]);
            float2 fb = unpack2(accB[cc]);
            resA[cc] = fa.x + fa.y;
            resB[cc] = fb.x + fb.y;
        }
        if (h == 1) {
#pragma unroll
            for (int cc = 0; cc < KK; cc++) {
                shh[r2 * 22 + cc] = resA[cc];
                shh[(64 + r2) * 22 + cc] = resB[cc];
            }
        }
        __syncthreads();
        float* shOut = shh + GR * 22;
        if (h == 0) {
#pragma unroll
            for (int cc = 0; cc < KK; cc++) {
                shOut[r2 * KK + cc] = resA[cc] + shh[r2 * 22 + cc] + bg[cc];
                shOut[(64 + r2) * KK + cc] =
                    resB[cc] + shh[(64 + r2) * 22 + cc] + bg[cc];
            }
        }
        __syncthreads();
        float* outp = out + rowBase * KK;
#pragma unroll
        for (int j = 0; j < (GR * KK) / GT; j++)
            outp[tid + j * GT] = shOut[tid + j * GT];

        // publish tile
        __threadfence();
        __syncthreads();
        if (tid == 0) atomicExch(&g_tflag[g], 1);
        return;
    }

    // ======================= CRF blocks (bx = batch) =======================
    const int b = bx;
    const int lane = tid & 31;
    const int w = tid >> 5;
    const int jj = (lane < KK) ? lane : KK - 1;

    __shared__ float s_uf[32], s_ub[32];
    __shared__ float s_cf, s_cb, s_num, s_end;

    const int len = seq_len_w(maskraw, b, lane);
    const int m = len >> 1;
    const int*   lab = labels + b * SS;
    const float* lg  = out + (size_t)b * SS * KK;

    if (w == 0) {
        // forward: t = 1..m, consuming tiles 0..3 as they land
        float tE[KK];
#pragma unroll
        for (int i = 0; i < KK; i++)
            tE[i] = __expf(trans[i * KK + jj]) * (1.f / 21.f);
        wait_flag(&g_tflag[4 * b]);
        __threadfence();
        float a0 = (lane < KK) ? (start_t[lane] + lg[lane]) : -1e30f;
        float m0 = a0;
#pragma unroll
        for (int o = 16; o; o >>= 1)
            m0 = fmaxf(m0, __shfl_xor_sync(FULLMASK, m0, o));
        float u = __expf(a0 - m0);
        float logC = m0;
        for (int k = 0; k < 4; k++) {
            int lo = 128 * k; if (lo < 1) lo = 1;
            int hi = 128 * k + 127; if (hi > m) hi = m;
            if (lo > hi) continue;
            if (k > 0) { wait_flag(&g_tflag[4 * b + k]); __threadfence(); }
            u = crf_run(u, logC, tE, lg, jj, lo, +1, hi - lo + 1);
        }
        s_uf[lane] = u;
        if (lane == 0) s_cf = logC;
    } else if (w == 1) {
        // backward: t = len-1 .. m+1, tiles descending
        float tEb[KK];
#pragma unroll
        for (int i = 0; i < KK; i++)
            tEb[i] = __expf(trans[jj * KK + i]) * (1.f / 21.f);
        float v = __expf(end_t[jj]);
        float logC = 0.f;
        for (int k = 3; k >= 0; k--) {
            int lo = 128 * k; if (lo < m + 1) lo = m + 1;
            int hi = 128 * k + 127; if (hi > len - 1) hi = len - 1;
            if (lo > hi) continue;
            wait_flag(&g_tflag[4 * b + k]);
            __threadfence();
            v = crf_run(v, logC, tEb, lg, jj, hi, -1, hi - lo + 1);
        }
        s_ub[lane] = v;
        if (lane == 0) s_cb = logC;
    } else if (w == 2) {
        // numerator, per tile
        float num = 0.f;
        for (int k = 0; k < 4; k++) {
            int lo = 128 * k;
            int hi = 128 * k + 127; if (hi > len - 1) hi = len - 1;
            if (lo > hi) continue;
            wait_flag(&g_tflag[4 * b + k]);
            __threadfence();
            for (int t = lo + lane; t <= hi; t += 32) {
                int lt = lab[t];
                float e = lg[t * KK + lt];
                num += (t == 0) ? (start_t[lt] + e)
                                : (e + trans[lab[t - 1] * KK + lt]);
            }
        }
#pragma unroll
        for (int o = 16; o; o >>= 1) num += __shfl_xor_sync(FULLMASK, num, o);
        if (lane == 0) {
            s_num = num;
            s_end = end_t[lab[len - 1]];
        }
    }

    __syncthreads();
    // all consumption done: reset this batch's tile flags for the next replay
    if (tid == 0) {
        g_tflag[4 * b + 0] = 0;
        g_tflag[4 * b + 1] = 0;
        g_tflag[4 * b + 2] = 0;
        g_tflag[4 * b + 3] = 0;
    }

    if (w == 0) {
        float p = (lane < KK) ? s_uf[lane] * s_ub[lane] : 0.f;
#pragma unroll
        for (int o = 16; o; o >>= 1) p += __shfl_xor_sync(FULLMASK, p, o);
        float logZ = __logf(p) + s_cf + s_cb;
        if (lane == 0) {
            g_partial[b] = logZ - (s_num + s_end);
            __threadfence();
            int old = atomicAdd(&g_ctr, 1);
            if (old == BB - 1) {
                __threadfence();
                float tot = 0.f;
                for (int i = 0; i < BB; i++) tot += g_partial[i];
                out_nll[0] = tot;
                g_ctr = 0;
            }
        }
    }
}

// ---------------------------------------------------------------------------
extern "C" void kernel_launch(void* const* d_in, const int* in_sizes, int n_in,
                              void* d_out, int out_size) {
    const float* hidden  = (const float*)d_in[0];
    const float* W       = (const float*)d_in[1];
    const float* b       = (const float*)d_in[2];
    const float* start_t = (const float*)d_in[3];
    const float* trans   = (const float*)d_in[4];
    const float* end_t   = (const float*)d_in[5];
    const int*   labels  = (const int*)d_in[6];
    const void*  mask    = (const void*)d_in[7];

    float* out     = (float*)d_out;
    float* out_nll = out + (out_size - 1);

    cudaFuncSetAttribute(fused_kernel,
                         cudaFuncAttributeMaxDynamicSharedMemorySize, GSMEM);

    fused_kernel<<<GEMMB0 + 256, GT, GSMEM>>>(hidden, W, b, start_t, trans,
                                              end_t, labels, mask, out,
                                              out_nll);
}